// round 7
// baseline (speedup 1.0000x reference)
#include <cuda_runtime.h>
#include <cuda_fp16.h>
#include <cstdint>

#define HID   32
#define EDIM  16
#define EH    128
#define TE    256
#define NTH   256
#define H_STRIDE 132
#define X_STRIDE 33

// ---- smem offsets (bytes) ----
#define OFF_X    0            // 256 x 33 f32 = 33792
#define OFF_B2   33792        // 4096 -> end 37888
#define OFF_BB0  38912        // 16384 B buffer 0 (overlays s_h after frag load)
#define OFF_BB1  55296        // 16384 B buffer 1
#define OFF_H    38912        // s_h fp32 [256][132] = 135168 -> end 174080 (transient)
#define OFF_EF   174080       // 256*16*4 = 16384
#define OFF_W1   190464       // 8192
#define OFF_B1   198656       // 512
#define SMEM_TOTAL 199680

// W2 rounded to fp16, fragment order: [nt(128)][ks(8)][lane(32)] = uint2{b01,b23}
__device__ uint2 g_Bfrag[128 * 8 * 32];

__device__ __forceinline__ uint32_t smem_u32(const void* p) {
    uint32_t a;
    asm("{ .reg .u64 t; cvta.to.shared.u64 t, %1; cvt.u32.u64 %0, t; }" : "=r"(a) : "l"(p));
    return a;
}
__device__ __forceinline__ uint32_t pkh(__half a, __half b) {
    __half2 v = __halves2half2(a, b);
    return *reinterpret_cast<uint32_t*>(&v);
}
// round pair of floats to fp16 (hi only)
__device__ __forceinline__ uint32_t rnd2h(float a, float b) {
    return pkh(__float2half_rn(a), __float2half_rn(b));
}
// split pair of floats into fp16 hi/lo packed regs (hi+lo covers ~22 mantissa bits)
__device__ __forceinline__ void split2h(float a, float b, uint32_t& hi, uint32_t& lo) {
    __half ha = __float2half_rn(a), hb = __float2half_rn(b);
    float ra = a - __half2float(ha);
    float rb = b - __half2float(hb);
    hi = pkh(ha, hb);
    lo = pkh(__float2half_rn(ra), __float2half_rn(rb));
}
__device__ __forceinline__ void mma_f16(float& d0, float& d1, float& d2, float& d3,
                                        uint32_t a0, uint32_t a1, uint32_t a2, uint32_t a3,
                                        uint32_t b0, uint32_t b1) {
    asm volatile(
        "mma.sync.aligned.m16n8k16.row.col.f32.f16.f16.f32 "
        "{%0,%1,%2,%3}, {%4,%5,%6,%7}, {%8,%9}, {%0,%1,%2,%3};"
        : "+f"(d0), "+f"(d1), "+f"(d2), "+f"(d3)
        : "r"(a0), "r"(a1), "r"(a2), "r"(a3), "r"(b0), "r"(b1));
}

// ---------------- prep: W2 -> fragment-ordered fp16 ----------------
__global__ void prep_b_kernel(const float* __restrict__ W2) {
    int idx = blockIdx.x * blockDim.x + threadIdx.x;
    if (idx >= 128 * 8 * 32) return;
    int lane = idx & 31, ks = (idx >> 5) & 7, nt = idx >> 8;
    int g = lane >> 2, c = lane & 3;
    int n = nt * 8 + g;
    int k0 = ks * 16 + 2 * c;
    float v0 = W2[(size_t)k0 * 1024 + n];
    float v1 = W2[(size_t)(k0 + 1) * 1024 + n];
    float v2 = W2[(size_t)(k0 + 8) * 1024 + n];
    float v3 = W2[(size_t)(k0 + 9) * 1024 + n];
    uint2 r;
    r.x = rnd2h(v0, v1);
    r.y = rnd2h(v2, v3);
    g_Bfrag[idx] = r;
}

__global__ void init_out_kernel(float* __restrict__ out,
                                const float* __restrict__ bias, int n) {
    int i = blockIdx.x * blockDim.x + threadIdx.x;
    if (i < n) out[i] = bias[i & (HID - 1)];
}

// ---------------- main fused kernel ----------------
__global__ __launch_bounds__(NTH, 1)
void mpnn_mma_kernel(const float* __restrict__ nf,
                     const float* __restrict__ ef,
                     const int*   __restrict__ src,
                     const int*   __restrict__ dst,
                     const float* __restrict__ W1,
                     const float* __restrict__ b1,
                     const float* __restrict__ b2,
                     float* __restrict__ out,
                     int E) {
    extern __shared__ __align__(1024) char sm[];
    const uint32_t sbase = smem_u32(sm);
    const int t = threadIdx.x;
    const int wid = t >> 5;
    const int lane = t & 31;
    const int e0g = blockIdx.x * TE;

    float* s_x  = (float*)(sm + OFF_X);
    float* s_b2 = (float*)(sm + OFF_B2);
    float* s_ef = (float*)(sm + OFF_EF);
    float* s_w1 = (float*)(sm + OFF_W1);
    float* s_b1 = (float*)(sm + OFF_B1);
    float* s_h  = (float*)(sm + OFF_H);

    // -------- phase 0: cooperative loads --------
    {
        const float4* efg = (const float4*)ef;
        float4* efs = (float4*)s_ef;
        for (int i = t; i < TE * EDIM / 4; i += NTH) {
            int ge = e0g + (i >> 2);
            float4 v = make_float4(0.f, 0.f, 0.f, 0.f);
            if (ge < E) v = efg[(size_t)e0g * 4 + i];
            efs[i] = v;
        }
        const float4* w1g = (const float4*)W1;
        float4* w1s = (float4*)s_w1;
        for (int i = t; i < EDIM * EH / 4; i += NTH) w1s[i] = w1g[i];
        if (t < EH / 4) ((float4*)s_b1)[t] = ((const float4*)b1)[t];
        for (int i = t; i < HID * HID / 4; i += NTH)
            ((float4*)s_b2)[i] = ((const float4*)b2)[i];
        const float4* nfg = (const float4*)nf;
        for (int j = t; j < TE * 8; j += NTH) {
            int e = j >> 3, c = j & 7, ge = e0g + e;
            float4 v = make_float4(0.f, 0.f, 0.f, 0.f);
            if (ge < E) { int sn = src[ge]; v = nfg[(size_t)sn * 8 + c]; }
            float* xr = s_x + e * X_STRIDE + c * 4;
            xr[0] = v.x; xr[1] = v.y; xr[2] = v.z; xr[3] = v.w;
        }
    }
    __syncthreads();

    // -------- phase A: h = relu(ef@W1+b1) -> s_h fp32 [256][132] --------
    {
        int e = t;   // one edge per thread
        float er[EDIM];
#pragma unroll
        for (int d = 0; d < EDIM; d++) er[d] = s_ef[e * EDIM + d];
#pragma unroll 4
        for (int j = 0; j < EH; j += 4) {
            float4 acc = *(const float4*)(s_b1 + j);
#pragma unroll
            for (int d = 0; d < EDIM; d++) {
                float4 w = *(const float4*)(s_w1 + d * EH + j);
                acc.x += er[d] * w.x; acc.y += er[d] * w.y;
                acc.z += er[d] * w.z; acc.w += er[d] * w.w;
            }
            s_h[e * H_STRIDE + j + 0] = fmaxf(acc.x, 0.f);
            s_h[e * H_STRIDE + j + 1] = fmaxf(acc.y, 0.f);
            s_h[e * H_STRIDE + j + 2] = fmaxf(acc.z, 0.f);
            s_h[e * H_STRIDE + j + 3] = fmaxf(acc.w, 0.f);
        }
    }
    __syncthreads();

    // -------- load A fragments (fp16 hi/lo) for 2 m-tiles into registers --------
    const int g  = lane >> 2;
    const int c4 = lane & 3;
    const int eb = wid * 32;
    const int er0 = eb + g,      er1 = er0 + 8;   // m-tile 0
    const int er2 = eb + 16 + g, er3 = er2 + 8;   // m-tile 1
    uint32_t ahi0[8][4], alo0[8][4], ahi1[8][4], alo1[8][4];
#pragma unroll
    for (int ks = 0; ks < 8; ks++) {
        int kb = ks * 16 + 2 * c4;
        float2 p;
        p = *(const float2*)(s_h + er0 * H_STRIDE + kb);     split2h(p.x, p.y, ahi0[ks][0], alo0[ks][0]);
        p = *(const float2*)(s_h + er1 * H_STRIDE + kb);     split2h(p.x, p.y, ahi0[ks][1], alo0[ks][1]);
        p = *(const float2*)(s_h + er0 * H_STRIDE + kb + 8); split2h(p.x, p.y, ahi0[ks][2], alo0[ks][2]);
        p = *(const float2*)(s_h + er1 * H_STRIDE + kb + 8); split2h(p.x, p.y, ahi0[ks][3], alo0[ks][3]);
        p = *(const float2*)(s_h + er2 * H_STRIDE + kb);     split2h(p.x, p.y, ahi1[ks][0], alo1[ks][0]);
        p = *(const float2*)(s_h + er3 * H_STRIDE + kb);     split2h(p.x, p.y, ahi1[ks][1], alo1[ks][1]);
        p = *(const float2*)(s_h + er2 * H_STRIDE + kb + 8); split2h(p.x, p.y, ahi1[ks][2], alo1[ks][2]);
        p = *(const float2*)(s_h + er3 * H_STRIDE + kb + 8); split2h(p.x, p.y, ahi1[ks][3], alo1[ks][3]);
    }
    __syncthreads();   // all A frags read before s_h region is reused for B

    // -------- mainloop: 128 n-tiles in 16 chunks, cp.async double-buffer --------
    auto stage = [&](int chunk) {
        const uint4* srcp = (const uint4*)g_Bfrag + chunk * 1024;
        uint32_t dstbase = sbase + ((chunk & 1) ? OFF_BB1 : OFF_BB0);
#pragma unroll
        for (int j = t; j < 1024; j += NTH) {
            uint32_t d = dstbase + j * 16;
            size_t gp = (size_t)__cvta_generic_to_global(srcp + j);
            asm volatile("cp.async.cg.shared.global [%0], [%1], 16;"
                         :: "r"(d), "l"(gp) : "memory");
        }
        asm volatile("cp.async.commit_group;" ::: "memory");
    };

    stage(0);
    stage(1);

    float acc[32];
#pragma unroll
    for (int i = 0; i < 32; i++) acc[i] = 0.f;

    for (int ch = 0; ch < 16; ch++) {
        asm volatile("cp.async.wait_group 1;" ::: "memory");
        __syncthreads();
        const uint2* bb = (const uint2*)(sm + ((ch & 1) ? OFF_BB1 : OFF_BB0));
#pragma unroll
        for (int ntl = 0; ntl < 8; ntl++) {
            int nt = ch * 8 + ntl;
            float dh0 = 0.f, dh1 = 0.f, dh2 = 0.f, dh3 = 0.f;
            float dl0 = 0.f, dl1 = 0.f, dl2 = 0.f, dl3 = 0.f;
            float eh0 = 0.f, eh1 = 0.f, eh2 = 0.f, eh3 = 0.f;
            float el0 = 0.f, el1 = 0.f, el2 = 0.f, el3 = 0.f;
            const uint2* bp = bb + ntl * 256 + lane;
#pragma unroll
            for (int ks = 0; ks < 8; ks++) {
                uint2 b = bp[ks * 32];
                mma_f16(dh0, dh1, dh2, dh3, ahi0[ks][0], ahi0[ks][1], ahi0[ks][2], ahi0[ks][3], b.x, b.y);
                mma_f16(dl0, dl1, dl2, dl3, alo0[ks][0], alo0[ks][1], alo0[ks][2], alo0[ks][3], b.x, b.y);
                mma_f16(eh0, eh1, eh2, eh3, ahi1[ks][0], ahi1[ks][1], ahi1[ks][2], ahi1[ks][3], b.x, b.y);
                mma_f16(el0, el1, el2, el3, alo1[ks][0], alo1[ks][1], alo1[ks][2], alo1[ks][3], b.x, b.y);
            }
            float d0 = dh0 + dl0, d1 = dh1 + dl1, d2 = dh2 + dl2, d3 = dh3 + dl3;
            float f0 = eh0 + el0, f1 = eh1 + el1, f2 = eh2 + el2, f3 = eh3 + el3;
            int i  = nt >> 2;
            int t4 = nt & 3;
            float xi0 = s_x[er0 * X_STRIDE + i];
            float xi1 = s_x[er1 * X_STRIDE + i];
            float xi2 = s_x[er2 * X_STRIDE + i];
            float xi3 = s_x[er3 * X_STRIDE + i];
            acc[t4 * 2 + 0]      = fmaf(xi0, d0, acc[t4 * 2 + 0]);
            acc[t4 * 2 + 1]      = fmaf(xi0, d1, acc[t4 * 2 + 1]);
            acc[8 + t4 * 2 + 0]  = fmaf(xi1, d2, acc[8 + t4 * 2 + 0]);
            acc[8 + t4 * 2 + 1]  = fmaf(xi1, d3, acc[8 + t4 * 2 + 1]);
            acc[16 + t4 * 2 + 0] = fmaf(xi2, f0, acc[16 + t4 * 2 + 0]);
            acc[16 + t4 * 2 + 1] = fmaf(xi2, f1, acc[16 + t4 * 2 + 1]);
            acc[24 + t4 * 2 + 0] = fmaf(xi3, f2, acc[24 + t4 * 2 + 0]);
            acc[24 + t4 * 2 + 1] = fmaf(xi3, f3, acc[24 + t4 * 2 + 1]);
        }
        __syncthreads();
        if (ch + 2 < 16) stage(ch + 2);
    }

    // -------- b2 term: msg[e,o] += sum_i x[e,i] * b2[i*32+o] --------
    const int ob = 2 * c4;
#pragma unroll 8
    for (int i = 0; i < HID; i++) {
        float xi0 = s_x[er0 * X_STRIDE + i];
        float xi1 = s_x[er1 * X_STRIDE + i];
        float xi2 = s_x[er2 * X_STRIDE + i];
        float xi3 = s_x[er3 * X_STRIDE + i];
#pragma unroll
        for (int t4 = 0; t4 < 4; t4++) {
            float2 bv = *(const float2*)(s_b2 + i * HID + t4 * 8 + ob);
            acc[t4 * 2 + 0]      = fmaf(xi0, bv.x, acc[t4 * 2 + 0]);
            acc[t4 * 2 + 1]      = fmaf(xi0, bv.y, acc[t4 * 2 + 1]);
            acc[8 + t4 * 2 + 0]  = fmaf(xi1, bv.x, acc[8 + t4 * 2 + 0]);
            acc[8 + t4 * 2 + 1]  = fmaf(xi1, bv.y, acc[8 + t4 * 2 + 1]);
            acc[16 + t4 * 2 + 0] = fmaf(xi2, bv.x, acc[16 + t4 * 2 + 0]);
            acc[16 + t4 * 2 + 1] = fmaf(xi2, bv.y, acc[16 + t4 * 2 + 1]);
            acc[24 + t4 * 2 + 0] = fmaf(xi3, bv.x, acc[24 + t4 * 2 + 0]);
            acc[24 + t4 * 2 + 1] = fmaf(xi3, bv.y, acc[24 + t4 * 2 + 1]);
        }
    }

    // -------- scatter-add --------
    {
        const int ers[4] = {er0, er1, er2, er3};
#pragma unroll
        for (int r = 0; r < 4; r++) {
            int ge = e0g + ers[r];
            if (ge < E) {
                int dn = dst[ge];
                float* op = out + (size_t)dn * HID;
#pragma unroll
                for (int t4 = 0; t4 < 4; t4++) {
                    atomicAdd(op + t4 * 8 + ob + 0, acc[r * 8 + t4 * 2 + 0]);
                    atomicAdd(op + t4 * 8 + ob + 1, acc[r * 8 + t4 * 2 + 1]);
                }
            }
        }
    }
}

extern "C" void kernel_launch(void* const* d_in, const int* in_sizes, int n_in,
                              void* d_out, int out_size) {
    const float* nf   = (const float*)d_in[0];
    const float* ef   = (const float*)d_in[1];
    const int*   src  = (const int*)d_in[2];
    const int*   dst  = (const int*)d_in[3];
    const float* W1   = (const float*)d_in[4];
    const float* b1   = (const float*)d_in[5];
    const float* W2   = (const float*)d_in[6];
    const float* b2   = (const float*)d_in[7];
    const float* bias = (const float*)d_in[8];
    float* out = (float*)d_out;

    const int E = in_sizes[2];

    cudaFuncSetAttribute(mpnn_mma_kernel,
                         cudaFuncAttributeMaxDynamicSharedMemorySize, SMEM_TOTAL);

    prep_b_kernel<<<128, 256>>>(W2);
    init_out_kernel<<<(out_size + 255) / 256, 256>>>(out, bias, out_size);

    int grid = (E + TE - 1) / TE;
    mpnn_mma_kernel<<<grid, NTH, SMEM_TOTAL>>>(nf, ef, src, dst, W1, b1, b2, out, E);
}

// round 8
// speedup vs baseline: 2.3082x; 2.3082x over previous
#include <cuda_runtime.h>
#include <cuda_fp16.h>
#include <cstdint>

#define HID   32
#define EDIM  16
#define EH    128
#define TE    256
#define NTH   256
#define H_STRIDE 132
#define X_STRIDE 33

// ---- smem offsets (bytes) ----
#define OFF_X    0            // 256 x 33 f32 = 33792
#define OFF_B2   33792        // 4096 -> end 37888
#define OFF_BB0  38912        // 16384 B buffer 0 (overlays s_h after frag load)
#define OFF_BB1  55296        // 16384 B buffer 1
#define OFF_H    38912        // s_h fp32 [256][132] = 135168 -> end 174080 (transient)
#define OFF_EF   174080       // 256*16*4 = 16384
#define OFF_W1   190464       // 8192
#define OFF_B1   198656       // 512
#define SMEM_TOTAL 199680

// W2 rounded to fp16, fragment order: [nt(128)][ks(8)][lane(32)] = uint2{b01,b23}
__device__ uint2 g_Bfrag[128 * 8 * 32];

__device__ __forceinline__ uint32_t smem_u32(const void* p) {
    uint32_t a;
    asm("{ .reg .u64 t; cvta.to.shared.u64 t, %1; cvt.u32.u64 %0, t; }" : "=r"(a) : "l"(p));
    return a;
}
__device__ __forceinline__ uint32_t pkh(__half a, __half b) {
    __half2 v = __halves2half2(a, b);
    return *reinterpret_cast<uint32_t*>(&v);
}
__device__ __forceinline__ uint32_t rnd2h(float a, float b) {
    return pkh(__float2half_rn(a), __float2half_rn(b));
}
__device__ __forceinline__ void mma_f16(float& d0, float& d1, float& d2, float& d3,
                                        uint32_t a0, uint32_t a1, uint32_t a2, uint32_t a3,
                                        uint32_t b0, uint32_t b1) {
    asm volatile(
        "mma.sync.aligned.m16n8k16.row.col.f32.f16.f16.f32 "
        "{%0,%1,%2,%3}, {%4,%5,%6,%7}, {%8,%9}, {%0,%1,%2,%3};"
        : "+f"(d0), "+f"(d1), "+f"(d2), "+f"(d3)
        : "r"(a0), "r"(a1), "r"(a2), "r"(a3), "r"(b0), "r"(b1));
}

// ---------------- prep: W2 -> fragment-ordered fp16 ----------------
__global__ void prep_b_kernel(const float* __restrict__ W2) {
    int idx = blockIdx.x * blockDim.x + threadIdx.x;
    if (idx >= 128 * 8 * 32) return;
    int lane = idx & 31, ks = (idx >> 5) & 7, nt = idx >> 8;
    int g = lane >> 2, c = lane & 3;
    int n = nt * 8 + g;
    int k0 = ks * 16 + 2 * c;
    float v0 = W2[(size_t)k0 * 1024 + n];
    float v1 = W2[(size_t)(k0 + 1) * 1024 + n];
    float v2 = W2[(size_t)(k0 + 8) * 1024 + n];
    float v3 = W2[(size_t)(k0 + 9) * 1024 + n];
    uint2 r;
    r.x = rnd2h(v0, v1);
    r.y = rnd2h(v2, v3);
    g_Bfrag[idx] = r;
}

__global__ void init_out_kernel(float* __restrict__ out,
                                const float* __restrict__ bias, int n) {
    int i = blockIdx.x * blockDim.x + threadIdx.x;
    if (i < n) out[i] = bias[i & (HID - 1)];
}

// ---------------- main fused kernel ----------------
__global__ __launch_bounds__(NTH, 1)
void mpnn_mma_kernel(const float* __restrict__ nf,
                     const float* __restrict__ ef,
                     const int*   __restrict__ src,
                     const int*   __restrict__ dst,
                     const float* __restrict__ W1,
                     const float* __restrict__ b1,
                     const float* __restrict__ b2,
                     float* __restrict__ out,
                     int E) {
    extern __shared__ __align__(1024) char sm[];
    const uint32_t sbase = smem_u32(sm);
    const int t = threadIdx.x;
    const int wid = t >> 5;
    const int lane = t & 31;
    const int e0g = blockIdx.x * TE;

    float* s_x  = (float*)(sm + OFF_X);
    float* s_b2 = (float*)(sm + OFF_B2);
    float* s_ef = (float*)(sm + OFF_EF);
    float* s_w1 = (float*)(sm + OFF_W1);
    float* s_b1 = (float*)(sm + OFF_B1);
    float* s_h  = (float*)(sm + OFF_H);

    // -------- phase 0: cooperative loads --------
    {
        const float4* efg = (const float4*)ef;
        float4* efs = (float4*)s_ef;
        for (int i = t; i < TE * EDIM / 4; i += NTH) {
            int ge = e0g + (i >> 2);
            float4 v = make_float4(0.f, 0.f, 0.f, 0.f);
            if (ge < E) v = efg[(size_t)e0g * 4 + i];
            efs[i] = v;
        }
        const float4* w1g = (const float4*)W1;
        float4* w1s = (float4*)s_w1;
        for (int i = t; i < EDIM * EH / 4; i += NTH) w1s[i] = w1g[i];
        if (t < EH / 4) ((float4*)s_b1)[t] = ((const float4*)b1)[t];
        for (int i = t; i < HID * HID / 4; i += NTH)
            ((float4*)s_b2)[i] = ((const float4*)b2)[i];
        const float4* nfg = (const float4*)nf;
        for (int j = t; j < TE * 8; j += NTH) {
            int e = j >> 3, c = j & 7, ge = e0g + e;
            float4 v = make_float4(0.f, 0.f, 0.f, 0.f);
            if (ge < E) { int sn = src[ge]; v = nfg[(size_t)sn * 8 + c]; }
            float* xr = s_x + e * X_STRIDE + c * 4;
            xr[0] = v.x; xr[1] = v.y; xr[2] = v.z; xr[3] = v.w;
        }
    }
    __syncthreads();

    // -------- phase A: h = relu(ef@W1+b1) -> s_h fp32 [256][132] --------
    {
        int e = t;   // one edge per thread
        float er[EDIM];
#pragma unroll
        for (int d = 0; d < EDIM; d++) er[d] = s_ef[e * EDIM + d];
#pragma unroll 4
        for (int j = 0; j < EH; j += 4) {
            float4 acc = *(const float4*)(s_b1 + j);
#pragma unroll
            for (int d = 0; d < EDIM; d++) {
                float4 w = *(const float4*)(s_w1 + d * EH + j);
                acc.x += er[d] * w.x; acc.y += er[d] * w.y;
                acc.z += er[d] * w.z; acc.w += er[d] * w.w;
            }
            s_h[e * H_STRIDE + j + 0] = fmaxf(acc.x, 0.f);
            s_h[e * H_STRIDE + j + 1] = fmaxf(acc.y, 0.f);
            s_h[e * H_STRIDE + j + 2] = fmaxf(acc.z, 0.f);
            s_h[e * H_STRIDE + j + 3] = fmaxf(acc.w, 0.f);
        }
    }
    __syncthreads();

    // -------- load A fragments (fp16, single pass) for 2 m-tiles --------
    const int g  = lane >> 2;
    const int c4 = lane & 3;
    const int eb = wid * 32;
    const int er0 = eb + g,      er1 = er0 + 8;   // m-tile 0
    const int er2 = eb + 16 + g, er3 = er2 + 8;   // m-tile 1
    uint32_t a0[8][4], a1[8][4];
#pragma unroll
    for (int ks = 0; ks < 8; ks++) {
        int kb = ks * 16 + 2 * c4;
        float2 p;
        p = *(const float2*)(s_h + er0 * H_STRIDE + kb);     a0[ks][0] = rnd2h(p.x, p.y);
        p = *(const float2*)(s_h + er1 * H_STRIDE + kb);     a0[ks][1] = rnd2h(p.x, p.y);
        p = *(const float2*)(s_h + er0 * H_STRIDE + kb + 8); a0[ks][2] = rnd2h(p.x, p.y);
        p = *(const float2*)(s_h + er1 * H_STRIDE + kb + 8); a0[ks][3] = rnd2h(p.x, p.y);
        p = *(const float2*)(s_h + er2 * H_STRIDE + kb);     a1[ks][0] = rnd2h(p.x, p.y);
        p = *(const float2*)(s_h + er3 * H_STRIDE + kb);     a1[ks][1] = rnd2h(p.x, p.y);
        p = *(const float2*)(s_h + er2 * H_STRIDE + kb + 8); a1[ks][2] = rnd2h(p.x, p.y);
        p = *(const float2*)(s_h + er3 * H_STRIDE + kb + 8); a1[ks][3] = rnd2h(p.x, p.y);
    }
    __syncthreads();   // all A frags read before s_h region is reused for B

    // -------- mainloop: 128 n-tiles in 16 chunks, cp.async double-buffer --------
    auto stage = [&](int chunk) {
        const uint4* srcp = (const uint4*)g_Bfrag + chunk * 1024;
        uint32_t dstbase = sbase + ((chunk & 1) ? OFF_BB1 : OFF_BB0);
#pragma unroll
        for (int j = t; j < 1024; j += NTH) {
            uint32_t d = dstbase + j * 16;
            size_t gp = (size_t)__cvta_generic_to_global(srcp + j);
            asm volatile("cp.async.cg.shared.global [%0], [%1], 16;"
                         :: "r"(d), "l"(gp) : "memory");
        }
        asm volatile("cp.async.commit_group;" ::: "memory");
    };

    stage(0);
    stage(1);

    float acc[32];
#pragma unroll
    for (int i = 0; i < 32; i++) acc[i] = 0.f;

    for (int ch = 0; ch < 16; ch++) {
        asm volatile("cp.async.wait_group 1;" ::: "memory");
        __syncthreads();
        const uint2* bb = (const uint2*)(sm + ((ch & 1) ? OFF_BB1 : OFF_BB0));
#pragma unroll
        for (int ntl = 0; ntl < 8; ntl++) {
            int nt = ch * 8 + ntl;
            float d0 = 0.f, d1 = 0.f, d2 = 0.f, d3 = 0.f;
            float f0 = 0.f, f1 = 0.f, f2 = 0.f, f3 = 0.f;
            const uint2* bp = bb + ntl * 256 + lane;
#pragma unroll
            for (int ks = 0; ks < 8; ks++) {
                uint2 b = bp[ks * 32];
                mma_f16(d0, d1, d2, d3, a0[ks][0], a0[ks][1], a0[ks][2], a0[ks][3], b.x, b.y);
                mma_f16(f0, f1, f2, f3, a1[ks][0], a1[ks][1], a1[ks][2], a1[ks][3], b.x, b.y);
            }
            int i  = nt >> 2;
            int t4 = nt & 3;
            float xi0 = s_x[er0 * X_STRIDE + i];
            float xi1 = s_x[er1 * X_STRIDE + i];
            float xi2 = s_x[er2 * X_STRIDE + i];
            float xi3 = s_x[er3 * X_STRIDE + i];
            acc[t4 * 2 + 0]      = fmaf(xi0, d0, acc[t4 * 2 + 0]);
            acc[t4 * 2 + 1]      = fmaf(xi0, d1, acc[t4 * 2 + 1]);
            acc[8 + t4 * 2 + 0]  = fmaf(xi1, d2, acc[8 + t4 * 2 + 0]);
            acc[8 + t4 * 2 + 1]  = fmaf(xi1, d3, acc[8 + t4 * 2 + 1]);
            acc[16 + t4 * 2 + 0] = fmaf(xi2, f0, acc[16 + t4 * 2 + 0]);
            acc[16 + t4 * 2 + 1] = fmaf(xi2, f1, acc[16 + t4 * 2 + 1]);
            acc[24 + t4 * 2 + 0] = fmaf(xi3, f2, acc[24 + t4 * 2 + 0]);
            acc[24 + t4 * 2 + 1] = fmaf(xi3, f3, acc[24 + t4 * 2 + 1]);
        }
        __syncthreads();
        if (ch + 2 < 16) stage(ch + 2);
    }

    // -------- b2 term: msg[e,o] += sum_i x[e,i] * b2[i*32+o] --------
    const int ob = 2 * c4;
#pragma unroll 8
    for (int i = 0; i < HID; i++) {
        float xi0 = s_x[er0 * X_STRIDE + i];
        float xi1 = s_x[er1 * X_STRIDE + i];
        float xi2 = s_x[er2 * X_STRIDE + i];
        float xi3 = s_x[er3 * X_STRIDE + i];
#pragma unroll
        for (int t4 = 0; t4 < 4; t4++) {
            float2 bv = *(const float2*)(s_b2 + i * HID + t4 * 8 + ob);
            acc[t4 * 2 + 0]      = fmaf(xi0, bv.x, acc[t4 * 2 + 0]);
            acc[t4 * 2 + 1]      = fmaf(xi0, bv.y, acc[t4 * 2 + 1]);
            acc[8 + t4 * 2 + 0]  = fmaf(xi1, bv.x, acc[8 + t4 * 2 + 0]);
            acc[8 + t4 * 2 + 1]  = fmaf(xi1, bv.y, acc[8 + t4 * 2 + 1]);
            acc[16 + t4 * 2 + 0] = fmaf(xi2, bv.x, acc[16 + t4 * 2 + 0]);
            acc[16 + t4 * 2 + 1] = fmaf(xi2, bv.y, acc[16 + t4 * 2 + 1]);
            acc[24 + t4 * 2 + 0] = fmaf(xi3, bv.x, acc[24 + t4 * 2 + 0]);
            acc[24 + t4 * 2 + 1] = fmaf(xi3, bv.y, acc[24 + t4 * 2 + 1]);
        }
    }

    // -------- scatter-add --------
    {
        const int ers[4] = {er0, er1, er2, er3};
#pragma unroll
        for (int r = 0; r < 4; r++) {
            int ge = e0g + ers[r];
            if (ge < E) {
                int dn = dst[ge];
                float* op = out + (size_t)dn * HID;
#pragma unroll
                for (int t4 = 0; t4 < 4; t4++) {
                    atomicAdd(op + t4 * 8 + ob + 0, acc[r * 8 + t4 * 2 + 0]);
                    atomicAdd(op + t4 * 8 + ob + 1, acc[r * 8 + t4 * 2 + 1]);
                }
            }
        }
    }
}

extern "C" void kernel_launch(void* const* d_in, const int* in_sizes, int n_in,
                              void* d_out, int out_size) {
    const float* nf   = (const float*)d_in[0];
    const float* ef   = (const float*)d_in[1];
    const int*   src  = (const int*)d_in[2];
    const int*   dst  = (const int*)d_in[3];
    const float* W1   = (const float*)d_in[4];
    const float* b1   = (const float*)d_in[5];
    const float* W2   = (const float*)d_in[6];
    const float* b2   = (const float*)d_in[7];
    const float* bias = (const float*)d_in[8];
    float* out = (float*)d_out;

    const int E = in_sizes[2];

    cudaFuncSetAttribute(mpnn_mma_kernel,
                         cudaFuncAttributeMaxDynamicSharedMemorySize, SMEM_TOTAL);

    prep_b_kernel<<<128, 256>>>(W2);
    init_out_kernel<<<(out_size + 255) / 256, 256>>>(out, bias, out_size);

    int grid = (E + TE - 1) / TE;
    mpnn_mma_kernel<<<grid, NTH, SMEM_TOTAL>>>(nf, ef, src, dst, W1, b1, b2, out, E);
}

// round 9
// speedup vs baseline: 2.7988x; 1.2125x over previous
#include <cuda_runtime.h>
#include <cuda_fp16.h>
#include <cstdint>

#define HID   32
#define EDIM  16
#define EH    128
#define TE    256
#define NTH   256
#define H2_STRIDE 136       // halves per h row; word-stride 68 ≡ 4 (mod 32) -> conflict-free frag reads
#define X_STRIDE 33

// ---- smem offsets (bytes) ----
#define OFF_X    0              // 256 x 33 f32 = 33792
#define OFF_H    33792          // fp16 h [256][136] = 69632 -> end 103424
#define OFF_W1   103424         // 8192
#define OFF_B1   111616         // 512
#define SMEM_TOTAL 112128       // <= 113.6KB -> 2 CTAs/SM
// overlays inside H region (valid after A-fragments are in registers)
#define OFF_BB0  OFF_H          // 16384
#define OFF_BB1  (OFF_H + 16384)
#define OFF_B2   (OFF_H + 32768)  // 4096

// W2 rounded to fp16, fragment order: [nt(128)][ks(8)][lane(32)] = uint2{b01,b23}
__device__ uint2 g_Bfrag[128 * 8 * 32];

__device__ __forceinline__ uint32_t smem_u32(const void* p) {
    uint32_t a;
    asm("{ .reg .u64 t; cvta.to.shared.u64 t, %1; cvt.u32.u64 %0, t; }" : "=r"(a) : "l"(p));
    return a;
}
__device__ __forceinline__ uint32_t pkh(__half a, __half b) {
    __half2 v = __halves2half2(a, b);
    return *reinterpret_cast<uint32_t*>(&v);
}
__device__ __forceinline__ uint32_t rnd2h(float a, float b) {
    return pkh(__float2half_rn(a), __float2half_rn(b));
}
__device__ __forceinline__ void mma_f16(float& d0, float& d1, float& d2, float& d3,
                                        uint32_t a0, uint32_t a1, uint32_t a2, uint32_t a3,
                                        uint32_t b0, uint32_t b1) {
    asm volatile(
        "mma.sync.aligned.m16n8k16.row.col.f32.f16.f16.f32 "
        "{%0,%1,%2,%3}, {%4,%5,%6,%7}, {%8,%9}, {%0,%1,%2,%3};"
        : "+f"(d0), "+f"(d1), "+f"(d2), "+f"(d3)
        : "r"(a0), "r"(a1), "r"(a2), "r"(a3), "r"(b0), "r"(b1));
}

// ---------------- prep: W2 -> fragment-ordered fp16 ----------------
__global__ void prep_b_kernel(const float* __restrict__ W2) {
    int idx = blockIdx.x * blockDim.x + threadIdx.x;
    if (idx >= 128 * 8 * 32) return;
    int lane = idx & 31, ks = (idx >> 5) & 7, nt = idx >> 8;
    int g = lane >> 2, c = lane & 3;
    int n = nt * 8 + g;
    int k0 = ks * 16 + 2 * c;
    float v0 = W2[(size_t)k0 * 1024 + n];
    float v1 = W2[(size_t)(k0 + 1) * 1024 + n];
    float v2 = W2[(size_t)(k0 + 8) * 1024 + n];
    float v3 = W2[(size_t)(k0 + 9) * 1024 + n];
    uint2 r;
    r.x = rnd2h(v0, v1);
    r.y = rnd2h(v2, v3);
    g_Bfrag[idx] = r;
}

__global__ void init_out_kernel(float* __restrict__ out,
                                const float* __restrict__ bias, int n) {
    int i = blockIdx.x * blockDim.x + threadIdx.x;
    if (i < n) out[i] = bias[i & (HID - 1)];
}

// ---------------- main fused kernel ----------------
__global__ __launch_bounds__(NTH, 2)
void mpnn_mma_kernel(const float* __restrict__ nf,
                     const float* __restrict__ ef,
                     const int*   __restrict__ src,
                     const int*   __restrict__ dst,
                     const float* __restrict__ W1,
                     const float* __restrict__ b1,
                     const float* __restrict__ b2,
                     float* __restrict__ out,
                     int E) {
    extern __shared__ __align__(1024) char sm[];
    const uint32_t sbase = smem_u32(sm);
    const int t = threadIdx.x;
    const int wid = t >> 5;
    const int lane = t & 31;
    const int e0g = blockIdx.x * TE;

    float*  s_x  = (float*)(sm + OFF_X);
    float*  s_b2 = (float*)(sm + OFF_B2);
    float*  s_w1 = (float*)(sm + OFF_W1);
    float*  s_b1 = (float*)(sm + OFF_B1);
    __half* s_h  = (__half*)(sm + OFF_H);

    // -------- phase 0: cooperative loads (W1, b1, x gather) --------
    {
        const float4* w1g = (const float4*)W1;
        float4* w1s = (float4*)s_w1;
        for (int i = t; i < EDIM * EH / 4; i += NTH) w1s[i] = w1g[i];
        if (t < EH / 4) ((float4*)s_b1)[t] = ((const float4*)b1)[t];
        const float4* nfg = (const float4*)nf;
        for (int j = t; j < TE * 8; j += NTH) {
            int e = j >> 3, c = j & 7, ge = e0g + e;
            float4 v = make_float4(0.f, 0.f, 0.f, 0.f);
            if (ge < E) { int sn = src[ge]; v = nfg[(size_t)sn * 8 + c]; }
            float* xr = s_x + e * X_STRIDE + c * 4;
            xr[0] = v.x; xr[1] = v.y; xr[2] = v.z; xr[3] = v.w;
        }
    }
    __syncthreads();

    // -------- phase A: h = relu(ef@W1+b1) -> s_h fp16 [256][136] --------
    {
        int e = t;               // one edge per thread
        int ge = e0g + e;
        float er[EDIM];
        if (ge < E) {
            const float4* efr = (const float4*)(ef + (size_t)ge * EDIM);
#pragma unroll
            for (int q = 0; q < 4; q++) {
                float4 v = efr[q];
                er[q * 4 + 0] = v.x; er[q * 4 + 1] = v.y;
                er[q * 4 + 2] = v.z; er[q * 4 + 3] = v.w;
            }
        } else {
#pragma unroll
            for (int d = 0; d < EDIM; d++) er[d] = 0.f;
        }
        uint32_t* hrow = (uint32_t*)(s_h + e * H2_STRIDE);
#pragma unroll 4
        for (int j = 0; j < EH; j += 4) {
            float4 acc = *(const float4*)(s_b1 + j);
#pragma unroll
            for (int d = 0; d < EDIM; d++) {
                float4 w = *(const float4*)(s_w1 + d * EH + j);
                acc.x += er[d] * w.x; acc.y += er[d] * w.y;
                acc.z += er[d] * w.z; acc.w += er[d] * w.w;
            }
            hrow[j / 2 + 0] = rnd2h(fmaxf(acc.x, 0.f), fmaxf(acc.y, 0.f));
            hrow[j / 2 + 1] = rnd2h(fmaxf(acc.z, 0.f), fmaxf(acc.w, 0.f));
        }
    }
    __syncthreads();

    // -------- load A fragments (fp16) for 2 m-tiles: plain u32 reads --------
    const int g  = lane >> 2;
    const int c4 = lane & 3;
    const int eb = wid * 32;
    const int er0 = eb + g,      er1 = er0 + 8;   // m-tile 0
    const int er2 = eb + 16 + g, er3 = er2 + 8;   // m-tile 1
    uint32_t a0[8][4], a1[8][4];
#pragma unroll
    for (int ks = 0; ks < 8; ks++) {
        int kb = ks * 16 + 2 * c4;
        a0[ks][0] = *(const uint32_t*)(s_h + er0 * H2_STRIDE + kb);
        a0[ks][1] = *(const uint32_t*)(s_h + er1 * H2_STRIDE + kb);
        a0[ks][2] = *(const uint32_t*)(s_h + er0 * H2_STRIDE + kb + 8);
        a0[ks][3] = *(const uint32_t*)(s_h + er1 * H2_STRIDE + kb + 8);
        a1[ks][0] = *(const uint32_t*)(s_h + er2 * H2_STRIDE + kb);
        a1[ks][1] = *(const uint32_t*)(s_h + er3 * H2_STRIDE + kb);
        a1[ks][2] = *(const uint32_t*)(s_h + er2 * H2_STRIDE + kb + 8);
        a1[ks][3] = *(const uint32_t*)(s_h + er3 * H2_STRIDE + kb + 8);
    }
    __syncthreads();   // all A frags in registers; h region is now reusable

    // b2 -> overlay slot in released h region
    for (int i = t; i < HID * HID / 4; i += NTH)
        ((float4*)s_b2)[i] = ((const float4*)b2)[i];

    // -------- mainloop: 128 n-tiles in 16 chunks, cp.async double-buffer --------
    auto stage = [&](int chunk) {
        const uint4* srcp = (const uint4*)g_Bfrag + chunk * 1024;
        uint32_t dstbase = sbase + ((chunk & 1) ? OFF_BB1 : OFF_BB0);
#pragma unroll
        for (int j = t; j < 1024; j += NTH) {
            uint32_t d = dstbase + j * 16;
            size_t gp = (size_t)__cvta_generic_to_global(srcp + j);
            asm volatile("cp.async.cg.shared.global [%0], [%1], 16;"
                         :: "r"(d), "l"(gp) : "memory");
        }
        asm volatile("cp.async.commit_group;" ::: "memory");
    };

    stage(0);
    stage(1);

    float acc[32];
#pragma unroll
    for (int i = 0; i < 32; i++) acc[i] = 0.f;

    for (int ch = 0; ch < 16; ch++) {
        asm volatile("cp.async.wait_group 1;" ::: "memory");
        __syncthreads();
        const uint2* bb = (const uint2*)(sm + ((ch & 1) ? OFF_BB1 : OFF_BB0));
#pragma unroll
        for (int ntl = 0; ntl < 8; ntl++) {
            int nt = ch * 8 + ntl;
            float d0 = 0.f, d1 = 0.f, d2 = 0.f, d3 = 0.f;
            float f0 = 0.f, f1 = 0.f, f2 = 0.f, f3 = 0.f;
            const uint2* bp = bb + ntl * 256 + lane;
#pragma unroll
            for (int ks = 0; ks < 8; ks++) {
                uint2 b = bp[ks * 32];
                mma_f16(d0, d1, d2, d3, a0[ks][0], a0[ks][1], a0[ks][2], a0[ks][3], b.x, b.y);
                mma_f16(f0, f1, f2, f3, a1[ks][0], a1[ks][1], a1[ks][2], a1[ks][3], b.x, b.y);
            }
            int i  = nt >> 2;
            int t4 = nt & 3;
            float xi0 = s_x[er0 * X_STRIDE + i];
            float xi1 = s_x[er1 * X_STRIDE + i];
            float xi2 = s_x[er2 * X_STRIDE + i];
            float xi3 = s_x[er3 * X_STRIDE + i];
            acc[t4 * 2 + 0]      = fmaf(xi0, d0, acc[t4 * 2 + 0]);
            acc[t4 * 2 + 1]      = fmaf(xi0, d1, acc[t4 * 2 + 1]);
            acc[8 + t4 * 2 + 0]  = fmaf(xi1, d2, acc[8 + t4 * 2 + 0]);
            acc[8 + t4 * 2 + 1]  = fmaf(xi1, d3, acc[8 + t4 * 2 + 1]);
            acc[16 + t4 * 2 + 0] = fmaf(xi2, f0, acc[16 + t4 * 2 + 0]);
            acc[16 + t4 * 2 + 1] = fmaf(xi2, f1, acc[16 + t4 * 2 + 1]);
            acc[24 + t4 * 2 + 0] = fmaf(xi3, f2, acc[24 + t4 * 2 + 0]);
            acc[24 + t4 * 2 + 1] = fmaf(xi3, f3, acc[24 + t4 * 2 + 1]);
        }
        __syncthreads();
        if (ch + 2 < 16) stage(ch + 2);
    }

    // -------- b2 term: msg[e,o] += sum_i x[e,i] * b2[i*32+o] --------
    const int ob = 2 * c4;
#pragma unroll 8
    for (int i = 0; i < HID; i++) {
        float xi0 = s_x[er0 * X_STRIDE + i];
        float xi1 = s_x[er1 * X_STRIDE + i];
        float xi2 = s_x[er2 * X_STRIDE + i];
        float xi3 = s_x[er3 * X_STRIDE + i];
#pragma unroll
        for (int t4 = 0; t4 < 4; t4++) {
            float2 bv = *(const float2*)(s_b2 + i * HID + t4 * 8 + ob);
            acc[t4 * 2 + 0]      = fmaf(xi0, bv.x, acc[t4 * 2 + 0]);
            acc[t4 * 2 + 1]      = fmaf(xi0, bv.y, acc[t4 * 2 + 1]);
            acc[8 + t4 * 2 + 0]  = fmaf(xi1, bv.x, acc[8 + t4 * 2 + 0]);
            acc[8 + t4 * 2 + 1]  = fmaf(xi1, bv.y, acc[8 + t4 * 2 + 1]);
            acc[16 + t4 * 2 + 0] = fmaf(xi2, bv.x, acc[16 + t4 * 2 + 0]);
            acc[16 + t4 * 2 + 1] = fmaf(xi2, bv.y, acc[16 + t4 * 2 + 1]);
            acc[24 + t4 * 2 + 0] = fmaf(xi3, bv.x, acc[24 + t4 * 2 + 0]);
            acc[24 + t4 * 2 + 1] = fmaf(xi3, bv.y, acc[24 + t4 * 2 + 1]);
        }
    }

    // -------- scatter-add --------
    {
        const int ers[4] = {er0, er1, er2, er3};
#pragma unroll
        for (int r = 0; r < 4; r++) {
            int ge = e0g + ers[r];
            if (ge < E) {
                int dn = dst[ge];
                float* op = out + (size_t)dn * HID;
#pragma unroll
                for (int t4 = 0; t4 < 4; t4++) {
                    atomicAdd(op + t4 * 8 + ob + 0, acc[r * 8 + t4 * 2 + 0]);
                    atomicAdd(op + t4 * 8 + ob + 1, acc[r * 8 + t4 * 2 + 1]);
                }
            }
        }
    }
}

extern "C" void kernel_launch(void* const* d_in, const int* in_sizes, int n_in,
                              void* d_out, int out_size) {
    const float* nf   = (const float*)d_in[0];
    const float* ef   = (const float*)d_in[1];
    const int*   src  = (const int*)d_in[2];
    const int*   dst  = (const int*)d_in[3];
    const float* W1   = (const float*)d_in[4];
    const float* b1   = (const float*)d_in[5];
    const float* W2   = (const float*)d_in[6];
    const float* b2   = (const float*)d_in[7];
    const float* bias = (const float*)d_in[8];
    float* out = (float*)d_out;

    const int E = in_sizes[2];

    cudaFuncSetAttribute(mpnn_mma_kernel,
                         cudaFuncAttributeMaxDynamicSharedMemorySize, SMEM_TOTAL);

    prep_b_kernel<<<128, 256>>>(W2);
    init_out_kernel<<<(out_size + 255) / 256, 256>>>(out, bias, out_size);

    int grid = (E + TE - 1) / TE;
    mpnn_mma_kernel<<<grid, NTH, SMEM_TOTAL>>>(nf, ef, src, dst, W1, b1, b2, out, E);
}